// round 8
// baseline (speedup 1.0000x reference)
#include <cuda_runtime.h>
#include <cstdint>
#include <cstddef>

// Problem constants
#define TT   464
#define HH   256
#define BB   64
#define H4   1024
#define MROWS (BB*TT)          // 29696
#define KFLAT (TT*HH)          // 118784
#define NKC   116              // dense split-K chunks (1024 k each)

// ---------------- scratch (static device globals; no allocation) -------------
__device__ float g_Z[(size_t)MROWS * H4];        // x@W + b   (121.6 MB)
__device__ float g_seq[(size_t)BB * KFLAT];      // lstm outputs (30.4 MB)
__device__ float g_part[(size_t)NKC * BB * HH];  // dense partials (7.6 MB)
__device__ float g_dummy[2 * BB * HH];           // fallback for hT/cT

// ---------------- f32x2 packed-math helpers ----------------------------------
__device__ __forceinline__ unsigned long long dup2(float x) {
    unsigned long long r;
    asm("mov.b64 %0, {%1,%1};" : "=l"(r) : "f"(x));
    return r;
}
__device__ __forceinline__ void fma2(unsigned long long& d,
                                     unsigned long long a, unsigned long long b) {
    asm("fma.rn.f32x2 %0, %1, %2, %0;" : "+l"(d) : "l"(a), "l"(b));
}
__device__ __forceinline__ unsigned long long add2(unsigned long long a,
                                                   unsigned long long b) {
    unsigned long long r;
    asm("add.rn.f32x2 %0, %1, %2;" : "=l"(r) : "l"(a), "l"(b));
    return r;
}
__device__ __forceinline__ void unpk(unsigned long long v, float& lo, float& hi) {
    asm("mov.b64 {%0,%1}, %2;" : "=f"(lo), "=f"(hi) : "l"(v));
}
__device__ __forceinline__ void lds_v2u64(unsigned long long& a, unsigned long long& b,
                                          unsigned addr) {
    asm volatile("ld.shared.v2.u64 {%0,%1}, [%2];" : "=l"(a), "=l"(b) : "r"(addr));
}
__device__ __forceinline__ void sts_v2u64(unsigned addr,
                                          unsigned long long a, unsigned long long b) {
    asm volatile("st.shared.v2.u64 [%0], {%1,%2};" :: "r"(addr), "l"(a), "l"(b));
}
__device__ __forceinline__ float4 lds_v4f(unsigned addr) {
    float4 v;
    asm volatile("ld.shared.v4.f32 {%0,%1,%2,%3}, [%4];"
                 : "=f"(v.x), "=f"(v.y), "=f"(v.z), "=f"(v.w) : "r"(addr));
    return v;
}

// =============================================================================
// Kernel A: Z = X@W + b.  M=29696, K=256, N=1024.
// BM=128, BN=64, BK=16, 256 threads.  Per thread 8 rows x 4 cols, rows packed
// in f32x2 pairs (A loaded as v2.u64 from transposed tile), B staged DUPLICATED
// (b,b) so FFMA2 needs no packing MOVs.  16 FFMA2 per thread per k.
// =============================================================================
__global__ __launch_bounds__(256) void gemm_xw_kernel(
    const float* __restrict__ X, const float* __restrict__ W,
    const float* __restrict__ bias)
{
    __shared__ float As[16 * 128];   // [k][m] transposed
    __shared__ float Bs2[16 * 128];  // [k][2n] duplicated (b,b)

    const int tid = threadIdx.x;
    const int tx = tid & 15;          // col quad: cols nBase + 4*tx .. +3
    const int ty = tid >> 4;          // row octet: rows mBase + 8*ty .. +7
    const int mBase = blockIdx.y * 128;
    const int nBase = blockIdx.x * 64;

    const int lmA = tid >> 1;         // 0..127
    const int lkA = (tid & 1) * 8;    // 0 or 8
    const int lkB = tid >> 4;         // 0..15
    const int lnB = (tid & 15) * 4;   // 0..60

    const unsigned as_b = (unsigned)__cvta_generic_to_shared(As);
    const unsigned bs_b = (unsigned)__cvta_generic_to_shared(Bs2);

    unsigned long long acc[4][4];
    #pragma unroll
    for (int i = 0; i < 4; i++)
        #pragma unroll
        for (int j = 0; j < 4; j++) acc[i][j] = 0ULL;

    for (int k0 = 0; k0 < 256; k0 += 16) {
        // stage A transposed
        float4 v0 = *reinterpret_cast<const float4*>(&X[(size_t)(mBase + lmA) * 256 + k0 + lkA]);
        float4 v1 = *reinterpret_cast<const float4*>(&X[(size_t)(mBase + lmA) * 256 + k0 + lkA + 4]);
        As[(lkA + 0) * 128 + lmA] = v0.x; As[(lkA + 1) * 128 + lmA] = v0.y;
        As[(lkA + 2) * 128 + lmA] = v0.z; As[(lkA + 3) * 128 + lmA] = v0.w;
        As[(lkA + 4) * 128 + lmA] = v1.x; As[(lkA + 5) * 128 + lmA] = v1.y;
        As[(lkA + 6) * 128 + lmA] = v1.z; As[(lkA + 7) * 128 + lmA] = v1.w;
        // stage B duplicated
        float4 w4 = *reinterpret_cast<const float4*>(&W[(size_t)(k0 + lkB) * H4 + nBase + lnB]);
        float4 d0 = make_float4(w4.x, w4.x, w4.y, w4.y);
        float4 d1 = make_float4(w4.z, w4.z, w4.w, w4.w);
        *reinterpret_cast<float4*>(&Bs2[lkB * 128 + 2 * lnB])     = d0;
        *reinterpret_cast<float4*>(&Bs2[lkB * 128 + 2 * lnB + 4]) = d1;
        __syncthreads();

        unsigned aA = as_b + (unsigned)(8 * ty) * 4;
        unsigned aB = bs_b + (unsigned)(8 * tx) * 4;
        #pragma unroll
        for (int k = 0; k < 16; k++) {
            unsigned long long a01, a23, a45, a67, b0, b1, b2, b3;
            lds_v2u64(a01, a23, aA);
            lds_v2u64(a45, a67, aA + 16);
            lds_v2u64(b0, b1, aB);
            lds_v2u64(b2, b3, aB + 16);
            aA += 512; aB += 512;
            fma2(acc[0][0], a01, b0); fma2(acc[0][1], a01, b1);
            fma2(acc[0][2], a01, b2); fma2(acc[0][3], a01, b3);
            fma2(acc[1][0], a23, b0); fma2(acc[1][1], a23, b1);
            fma2(acc[1][2], a23, b2); fma2(acc[1][3], a23, b3);
            fma2(acc[2][0], a45, b0); fma2(acc[2][1], a45, b1);
            fma2(acc[2][2], a45, b2); fma2(acc[2][3], a45, b3);
            fma2(acc[3][0], a67, b0); fma2(acc[3][1], a67, b1);
            fma2(acc[3][2], a67, b2); fma2(acc[3][3], a67, b3);
        }
        __syncthreads();
    }

    float4 bv = *reinterpret_cast<const float4*>(&bias[nBase + 4 * tx]);
    #pragma unroll
    for (int rp = 0; rp < 4; rp++) {
        float lo0, hi0, lo1, hi1, lo2, hi2, lo3, hi3;
        unpk(acc[rp][0], lo0, hi0); unpk(acc[rp][1], lo1, hi1);
        unpk(acc[rp][2], lo2, hi2); unpk(acc[rp][3], lo3, hi3);
        const int row0 = mBase + 8 * ty + 2 * rp;
        float4 o0 = make_float4(lo0 + bv.x, lo1 + bv.y, lo2 + bv.z, lo3 + bv.w);
        float4 o1 = make_float4(hi0 + bv.x, hi1 + bv.y, hi2 + bv.z, hi3 + bv.w);
        *reinterpret_cast<float4*>(&g_Z[(size_t)row0 * H4 + nBase + 4 * tx])       = o0;
        *reinterpret_cast<float4*>(&g_Z[(size_t)(row0 + 1) * H4 + nBase + 4 * tx]) = o1;
    }
}

// =============================================================================
// Kernel B: LSTM recurrence.  16 clusters x 8 CTAs, 256 threads each.
// CTA rank r holds 128 U columns (gate-interleaved) resident in SMEM, k-major
// layout Usk[k][128] so that 4 batch-lanes per warp broadcast-share each u load
// (u wavefronts at the data minimum).  h kept in padded-stride hbuf (264 floats
// -> conflict-free across 4 batches).  Dot computed as f32x2 column-pairs with
// a k-split of 2 (threads 256 = 2 kh x 32 colquads x 4 batches); partials
// merged through zbuf.  New h scattered to all 8 peers via DSMEM; one
// barrier.cluster per step, double-buffered hbuf.
// =============================================================================
#define CLSZ 8
#define GBAT 4
#define HSTR 264
#define USK_FLOATS (256 * 128)                 // 32768
#define HB_FLOATS  (2 * GBAT * HSTR)           // 2112
#define ZB_FLOATS  (2 * GBAT * 128)            // 1024
#define LSTM_SMEM_BYTES ((USK_FLOATS + HB_FLOATS + ZB_FLOATS) * 4)  // 143616

__global__ __cluster_dims__(CLSZ, 1, 1) __launch_bounds__(256, 1)
void lstm_kernel(const float* __restrict__ U,
                 const float* __restrict__ h0, const float* __restrict__ c0,
                 float* __restrict__ outHT, float* __restrict__ outCT)
{
    extern __shared__ float sm[];
    float* Usk  = sm;                       // [256][128]  k-major
    float* hbuf = sm + USK_FLOATS;          // [2][4][HSTR]
    float* zbuf = hbuf + HB_FLOATS;         // [2][4][128]  kh-partials

    const int tid = threadIdx.x;
    unsigned rank_u;
    asm("mov.u32 %0, %%cluster_ctarank;" : "=r"(rank_u));
    const int r   = (int)rank_u;
    const int gb0 = (blockIdx.x >> 3) * GBAT;

    // stage U slice, k-major: Usk[k][l] = U[k][(l>>5)*256 + r*32 + (l&31)]
    for (int idx = tid; idx < USK_FLOATS; idx += 256) {
        int k = idx >> 7, l = idx & 127;
        Usk[idx] = U[(size_t)k * H4 + (l >> 5) * 256 + r * 32 + (l & 31)];
    }
    // h0 into parity 0
    for (int idx = tid; idx < GBAT * HH; idx += 256) {
        int b = idx >> 8, k = idx & 255;
        hbuf[b * HSTR + k] = h0[(size_t)(gb0 + b) * HH + k];
    }

    // dot-phase roles: warp w: kh = w>>2; lanes: b = lane>>3, cgl = lane&7;
    // colquad cg = (w&3)*8 + cgl  (cols 4cg..4cg+3)
    const int w    = tid >> 5;
    const int lane = tid & 31;
    const int kh   = w >> 2;
    const int cg   = (w & 3) * 8 + (lane & 7);
    const int bd_  = lane >> 3;

    const unsigned sm_b = (unsigned)__cvta_generic_to_shared(sm);
    const unsigned hb_b = sm_b + USK_FLOATS * 4;
    const unsigned zb_b = hb_b + HB_FLOATS * 4;
    const unsigned ua0  = sm_b + (unsigned)((kh * 128) * 128 + 4 * cg) * 4;
    const unsigned ha0  = hb_b + (unsigned)(bd_ * HSTR + kh * 128) * 4;
    const unsigned zst  = zb_b + (unsigned)((kh * 4 + bd_) * 128 + 4 * cg) * 4;

    // epilogue roles (tid < 128)
    const int bc = tid >> 5;
    const int dc = tid & 31;
    const int hdim = r * 32 + dc;
    float creg = 0.0f;
    const float* zp = g_Z + (size_t)(gb0 + bc) * TT * H4 + hdim;
    if (tid < 128) creg = c0[(size_t)(gb0 + bc) * HH + hdim];

    __syncthreads();
    asm volatile("barrier.cluster.arrive.aligned;" ::: "memory");
    asm volatile("barrier.cluster.wait.aligned;"  ::: "memory");

    for (int step = 0; step < TT; step++) {
        const int p = step & 1;
        // prefetch x@W+b contributions (consumed after the ~1400-cyc dot)
        float z0 = 0.f, z1 = 0.f, z2 = 0.f, z3 = 0.f;
        if (tid < 128) {
            const float* zr = zp + (size_t)step * H4;
            z0 = __ldg(zr);       z1 = __ldg(zr + 256);
            z2 = __ldg(zr + 512); z3 = __ldg(zr + 768);
        }

        unsigned ua = ua0;
        unsigned ha = ha0 + (unsigned)(p * (GBAT * HSTR)) * 4;
        unsigned long long a00 = 0, a01 = 0, a10 = 0, a11 = 0;
        #pragma unroll 4
        for (int it = 0; it < 32; it++) {
            float4 h4 = lds_v4f(ha); ha += 16;
            unsigned long long hx0 = dup2(h4.x), hx1 = dup2(h4.y);
            unsigned long long hx2 = dup2(h4.z), hx3 = dup2(h4.w);
            unsigned long long uA, uB;
            lds_v2u64(uA, uB, ua);         fma2(a00, uA, hx0); fma2(a01, uB, hx0);
            lds_v2u64(uA, uB, ua + 512);   fma2(a10, uA, hx1); fma2(a11, uB, hx1);
            lds_v2u64(uA, uB, ua + 1024);  fma2(a00, uA, hx2); fma2(a01, uB, hx2);
            lds_v2u64(uA, uB, ua + 1536);  fma2(a10, uA, hx3); fma2(a11, uB, hx3);
            ua += 2048;
        }
        unsigned long long c0p = add2(a00, a10);
        unsigned long long c1p = add2(a01, a11);
        sts_v2u64(zst, c0p, c1p);
        __syncthreads();

        if (tid < 128) {
            const float* zb = zbuf + bc * 128 + dc;
            float zi = zb[0]  + zb[512]      + z0;
            float zf = zb[32] + zb[512 + 32] + z1;
            float zg = zb[64] + zb[512 + 64] + z2;
            float zo = zb[96] + zb[512 + 96] + z3;
            float ig = 1.0f / (1.0f + __expf(-zi));
            float fg = 1.0f / (1.0f + __expf(-zf));
            creg = fg * creg + ig * fmaxf(zg, 0.0f);
            float hv = (1.0f / (1.0f + __expf(-zo))) * fmaxf(creg, 0.0f);

            g_seq[(size_t)(gb0 + bc) * KFLAT + step * HH + hdim] = hv;

            unsigned la = hb_b + (unsigned)(((p ^ 1) * GBAT + bc) * HSTR + hdim) * 4;
            #pragma unroll
            for (int rk = 0; rk < CLSZ; rk++) {
                unsigned ra;
                asm volatile("mapa.shared::cluster.u32 %0, %1, %2;"
                             : "=r"(ra) : "r"(la), "r"(rk));
                asm volatile("st.shared::cluster.f32 [%0], %1;"
                             :: "r"(ra), "f"(hv) : "memory");
            }
            if (step == TT - 1) {
                outHT[(size_t)(gb0 + bc) * HH + hdim] = hv;
                outCT[(size_t)(gb0 + bc) * HH + hdim] = creg;
            }
        }
        asm volatile("barrier.cluster.arrive.aligned;" ::: "memory");
        asm volatile("barrier.cluster.wait.aligned;"  ::: "memory");
    }
}

// =============================================================================
// Kernel C: dense split-K partials.  M=64, N=256 (2 tiles of 128), K=118784
// (116 chunks of 1024).  BM=64, BN=128, BK=16, 256 threads, 8 rows x 4 cols
// per thread with row-paired FFMA2 (A v2.u64, B duplicated).
// =============================================================================
__global__ __launch_bounds__(256) void gemm_dense_kernel(const float* __restrict__ Wd)
{
    __shared__ float As[16 * 64];     // [k][m]
    __shared__ float Bs2[16 * 256];   // [k][2n] duplicated

    const int tid = threadIdx.x;
    const int tx = tid & 31;          // cols nBase + 4*tx .. +3
    const int ty = tid >> 5;          // rows 8*ty .. +7
    const int nBase = blockIdx.x * 128;
    const int kc = blockIdx.y;
    const int kBase = kc * 1024;

    const int lmA = tid >> 2;          // 0..63
    const int lkA = (tid & 3) * 4;     // 0,4,8,12
    const int lkB = tid >> 4;          // 0..15
    const int lnB = (tid & 15) * 8;    // 0..120

    const unsigned as_b = (unsigned)__cvta_generic_to_shared(As);
    const unsigned bs_b = (unsigned)__cvta_generic_to_shared(Bs2);

    unsigned long long acc[4][4];
    #pragma unroll
    for (int i = 0; i < 4; i++)
        #pragma unroll
        for (int j = 0; j < 4; j++) acc[i][j] = 0ULL;

    for (int it = 0; it < 64; it++) {
        const int k0 = kBase + it * 16;
        float4 av = *reinterpret_cast<const float4*>(&g_seq[(size_t)lmA * KFLAT + k0 + lkA]);
        As[(lkA + 0) * 64 + lmA] = av.x; As[(lkA + 1) * 64 + lmA] = av.y;
        As[(lkA + 2) * 64 + lmA] = av.z; As[(lkA + 3) * 64 + lmA] = av.w;

        float4 w0 = *reinterpret_cast<const float4*>(&Wd[(size_t)(k0 + lkB) * HH + nBase + lnB]);
        float4 w1 = *reinterpret_cast<const float4*>(&Wd[(size_t)(k0 + lkB) * HH + nBase + lnB + 4]);
        *reinterpret_cast<float4*>(&Bs2[lkB * 256 + 2 * lnB])      = make_float4(w0.x, w0.x, w0.y, w0.y);
        *reinterpret_cast<float4*>(&Bs2[lkB * 256 + 2 * lnB + 4])  = make_float4(w0.z, w0.z, w0.w, w0.w);
        *reinterpret_cast<float4*>(&Bs2[lkB * 256 + 2 * lnB + 8])  = make_float4(w1.x, w1.x, w1.y, w1.y);
        *reinterpret_cast<float4*>(&Bs2[lkB * 256 + 2 * lnB + 12]) = make_float4(w1.z, w1.z, w1.w, w1.w);
        __syncthreads();

        unsigned aA = as_b + (unsigned)(8 * ty) * 4;
        unsigned aB = bs_b + (unsigned)(8 * tx) * 4;
        #pragma unroll
        for (int k = 0; k < 16; k++) {
            unsigned long long a01, a23, a45, a67, b0, b1, b2, b3;
            lds_v2u64(a01, a23, aA);
            lds_v2u64(a45, a67, aA + 16);
            lds_v2u64(b0, b1, aB);
            lds_v2u64(b2, b3, aB + 16);
            aA += 256; aB += 1024;
            fma2(acc[0][0], a01, b0); fma2(acc[0][1], a01, b1);
            fma2(acc[0][2], a01, b2); fma2(acc[0][3], a01, b3);
            fma2(acc[1][0], a23, b0); fma2(acc[1][1], a23, b1);
            fma2(acc[1][2], a23, b2); fma2(acc[1][3], a23, b3);
            fma2(acc[2][0], a45, b0); fma2(acc[2][1], a45, b1);
            fma2(acc[2][2], a45, b2); fma2(acc[2][3], a45, b3);
            fma2(acc[3][0], a67, b0); fma2(acc[3][1], a67, b1);
            fma2(acc[3][2], a67, b2); fma2(acc[3][3], a67, b3);
        }
        __syncthreads();
    }

    #pragma unroll
    for (int rp = 0; rp < 4; rp++) {
        float lo0, hi0, lo1, hi1, lo2, hi2, lo3, hi3;
        unpk(acc[rp][0], lo0, hi0); unpk(acc[rp][1], lo1, hi1);
        unpk(acc[rp][2], lo2, hi2); unpk(acc[rp][3], lo3, hi3);
        const int row0 = 8 * ty + 2 * rp;
        *reinterpret_cast<float4*>(&g_part[((size_t)kc * 64 + row0) * HH + nBase + 4 * tx]) =
            make_float4(lo0, lo1, lo2, lo3);
        *reinterpret_cast<float4*>(&g_part[((size_t)kc * 64 + row0 + 1) * HH + nBase + 4 * tx]) =
            make_float4(hi0, hi1, hi2, hi3);
    }
}

// Final reduce + bias + relu -> core_output.  256 CTAs x 128 thr, k-split 2.
__global__ __launch_bounds__(128) void reduce_dense_kernel(
    const float* __restrict__ bd, float* __restrict__ outCore)
{
    __shared__ float s2[128];
    const int b  = blockIdx.x >> 2;
    const int nq = blockIdx.x & 3;
    const int n  = nq * 64 + (threadIdx.x & 63);
    const int kh = threadIdx.x >> 6;
    float s = 0.0f;
    #pragma unroll 8
    for (int kc = kh; kc < NKC; kc += 2)
        s += g_part[((size_t)kc * 64 + b) * HH + n];
    s2[threadIdx.x] = s;
    __syncthreads();
    if (kh == 0)
        outCore[(size_t)b * HH + n] = fmaxf(s + s2[threadIdx.x + 64] + bd[n], 0.0f);
}

// =============================================================================
extern "C" void kernel_launch(void* const* d_in, const int* in_sizes, int n_in,
                              void* d_out, int out_size)
{
    const float* X  = (const float*)d_in[0];  // [64,464,256]
    const float* h0 = (const float*)d_in[1];  // [64,256]
    const float* c0 = (const float*)d_in[2];  // [64,256]
    const float* W  = (const float*)d_in[3];  // [256,1024]
    const float* U  = (const float*)d_in[4];  // [256,1024]
    const float* bb = (const float*)d_in[5];  // [1024]
    const float* Wd = (const float*)d_in[6];  // [118784,256]
    const float* bd = (const float*)d_in[7];  // [256]
    float* out = (float*)d_out;

    float* outCore = out;
    float* outHT;
    float* outCT;
    if (out_size >= 3 * BB * HH) {
        outHT = out + BB * HH;
        outCT = out + 2 * BB * HH;
    } else {
        float* dummy = nullptr;
        cudaGetSymbolAddress((void**)&dummy, g_dummy);
        outHT = dummy;
        outCT = dummy + BB * HH;
    }

    cudaFuncSetAttribute(lstm_kernel,
                         cudaFuncAttributeMaxDynamicSharedMemorySize,
                         LSTM_SMEM_BYTES);

    // 1) Z = X@W + b
    gemm_xw_kernel<<<dim3(H4 / 64, MROWS / 128), 256>>>(X, W, bb);

    // 2) recurrence (16 clusters x 8 CTAs)
    lstm_kernel<<<128, 256, LSTM_SMEM_BYTES>>>(U, h0, c0, outHT, outCT);

    // 3) dense split-K + reduce
    gemm_dense_kernel<<<dim3(2, NKC), 256>>>(Wd);
    reduce_dense_kernel<<<256, 128>>>(bd, outCore);
}

// round 13
// speedup vs baseline: 1.1891x; 1.1891x over previous
#include <cuda_runtime.h>
#include <cstdint>
#include <cstddef>

// Problem constants
#define TT   464
#define HH   256
#define BB   64
#define H4   1024
#define MROWS (BB*TT)          // 29696
#define KFLAT (TT*HH)          // 118784
#define NKC   116              // dense split-K chunks (1024 k each)

// ---------------- scratch (static device globals; no allocation) -------------
__device__ float g_Z[(size_t)MROWS * H4];        // x@W + b   (121.6 MB)
__device__ float g_seq[(size_t)BB * KFLAT];      // lstm outputs (30.4 MB)
__device__ float g_part[(size_t)NKC * BB * HH];  // dense partials (7.6 MB)
__device__ float g_dummy[2 * BB * HH];           // fallback for hT/cT

__device__ __forceinline__ float sigmoidf_(float x) {
    return 1.0f / (1.0f + expf(-x));
}

// =============================================================================
// Kernel A: Z[m][n] = sum_k X[m][k]*W[k][n] + bias[n]
// M=29696, K=256, N=1024.  BM=128, BN=64, BK=16, 256 threads, 8x4 per thread.
// Register double-buffering: next tile's LDGs issued before the FFMA loop so
// LDG->STS latency is hidden behind compute.
// =============================================================================
__global__ __launch_bounds__(256) void gemm_xw_kernel(
    const float* __restrict__ X, const float* __restrict__ W,
    const float* __restrict__ bias)
{
    __shared__ float As[16][128];
    __shared__ float Bs[16][64];

    const int tid = threadIdx.x;
    const int tx = tid & 15;          // 0..15  -> 4 cols
    const int ty = tid >> 4;          // 0..15  -> 8 rows
    const int mBase = blockIdx.y * 128;
    const int nBase = blockIdx.x * 64;

    const int lmA = tid >> 1;         // 0..127
    const int lkA = (tid & 1) * 8;    // 0 or 8
    const int lkB = tid >> 4;         // 0..15
    const int lnB = (tid & 15) * 4;

    float acc[8][4];
    #pragma unroll
    for (int i = 0; i < 8; i++)
        #pragma unroll
        for (int j = 0; j < 4; j++) acc[i][j] = 0.0f;

    const float* xRow = &X[(size_t)(mBase + lmA) * 256 + lkA];
    const float* wRow = &W[(size_t)lkB * H4 + nBase + lnB];

    // prefetch tile 0 into registers
    float4 pv0 = *reinterpret_cast<const float4*>(xRow);
    float4 pv1 = *reinterpret_cast<const float4*>(xRow + 4);
    float4 pw  = *reinterpret_cast<const float4*>(wRow);

    #pragma unroll 1
    for (int t = 0; t < 16; t++) {
        // commit staged registers to SMEM (A transposed)
        As[lkA + 0][lmA] = pv0.x; As[lkA + 1][lmA] = pv0.y;
        As[lkA + 2][lmA] = pv0.z; As[lkA + 3][lmA] = pv0.w;
        As[lkA + 4][lmA] = pv1.x; As[lkA + 5][lmA] = pv1.y;
        As[lkA + 6][lmA] = pv1.z; As[lkA + 7][lmA] = pv1.w;
        *reinterpret_cast<float4*>(&Bs[lkB][lnB]) = pw;
        __syncthreads();

        // issue next tile's global loads (consumed after the FFMA loop)
        if (t < 15) {
            const int k0 = (t + 1) * 16;
            pv0 = *reinterpret_cast<const float4*>(xRow + k0);
            pv1 = *reinterpret_cast<const float4*>(xRow + k0 + 4);
            pw  = *reinterpret_cast<const float4*>(wRow + (size_t)k0 * H4);
        }

        #pragma unroll
        for (int k = 0; k < 16; k++) {
            float4 a0 = *reinterpret_cast<const float4*>(&As[k][ty * 8]);
            float4 a1 = *reinterpret_cast<const float4*>(&As[k][ty * 8 + 4]);
            float4 b0 = *reinterpret_cast<const float4*>(&Bs[k][tx * 4]);
            float ar[8] = {a0.x, a0.y, a0.z, a0.w, a1.x, a1.y, a1.z, a1.w};
            float br[4] = {b0.x, b0.y, b0.z, b0.w};
            #pragma unroll
            for (int i = 0; i < 8; i++)
                #pragma unroll
                for (int j = 0; j < 4; j++)
                    acc[i][j] = fmaf(ar[i], br[j], acc[i][j]);
        }
        __syncthreads();
    }

    float4 bv = *reinterpret_cast<const float4*>(&bias[nBase + tx * 4]);
    #pragma unroll
    for (int i = 0; i < 8; i++) {
        float4 o;
        o.x = acc[i][0] + bv.x; o.y = acc[i][1] + bv.y;
        o.z = acc[i][2] + bv.z; o.w = acc[i][3] + bv.w;
        *reinterpret_cast<float4*>(&g_Z[(size_t)(mBase + ty * 8 + i) * H4 + nBase + tx * 4]) = o;
    }
}

// =============================================================================
// Kernel B: LSTM recurrence (exact structure of the R5 kernel that passed at
// 3203us).  16 clusters x 8 CTAs, 256 threads each.  CTA rank r holds U
// columns { g*256 + r*32 + d } resident in SMEM (transposed, stride 260 ->
// conflict-free LDS.128), owns h-dims [r*32, r*32+32).  New h scattered to
// all 8 peers via DSMEM, double-buffered, one fused cluster barrier per step.
// =============================================================================
#define CLSZ 8
#define GBAT 4
#define USTRIDE 260
#define US_FLOATS (128 * USTRIDE)          // 33280
#define HBUF_FLOATS (2 * GBAT * HH)        // 2048
#define ZBUF_FLOATS (4 * 32 * GBAT)        // 512
#define LSTM_SMEM_BYTES ((US_FLOATS + HBUF_FLOATS + ZBUF_FLOATS) * 4)  // 143360

__global__ __cluster_dims__(CLSZ, 1, 1) __launch_bounds__(256, 1)
void lstm_kernel(const float* __restrict__ U,
                 const float* __restrict__ h0, const float* __restrict__ c0,
                 float* __restrict__ outHT, float* __restrict__ outCT)
{
    extern __shared__ float sm[];
    float* Us   = sm;                       // [128][260]
    float* hbuf = sm + US_FLOATS;           // [2][4][256]
    float* zbuf = hbuf + HBUF_FLOATS;       // [4][32][4]

    const int tid = threadIdx.x;
    uint32_t rank_u;
    asm("mov.u32 %0, %%cluster_ctarank;" : "=r"(rank_u));
    const int r   = (int)rank_u;
    const int cid = blockIdx.x / CLSZ;
    const int gb0 = cid * GBAT;

    // ---- stage U slice into SMEM, transposed [col][k] ----
    for (int idx = tid; idx < 256 * 128; idx += 256) {
        int k = idx >> 7;
        int l = idx & 127;
        int gcol = (l >> 5) * 256 + r * 32 + (l & 31);
        Us[l * USTRIDE + k] = U[(size_t)k * H4 + gcol];
    }
    // ---- h0 into hbuf parity 0 ----
    for (int idx = tid; idx < GBAT * HH; idx += 256) {
        int b = idx >> 8;
        int k = idx & 255;
        hbuf[b * HH + k] = h0[(size_t)(gb0 + b) * HH + k];
    }
    // ---- c state in registers (threads 0..127 own (dim, batch)) ----
    const int bc = tid >> 5;   // valid for tid<128: 0..3
    const int dc = tid & 31;
    float creg = 0.0f;
    if (tid < 128) creg = c0[(size_t)(gb0 + bc) * HH + r * 32 + dc];

    // dot-phase mapping
    const int l    = tid & 127;
    const int bp   = tid >> 7;       // batch pair: 0 -> {0,1}, 1 -> {2,3}
    const int gate = l >> 5;
    const int dl   = l & 31;
    const int gcol = gate * 256 + r * 32 + dl;

    const uint32_t hb_base = (uint32_t)__cvta_generic_to_shared(hbuf);

    asm volatile("barrier.cluster.arrive.aligned;\n" ::: "memory");
    asm volatile("barrier.cluster.wait.aligned;\n" ::: "memory");

    for (int step = 0; step < TT; step++) {
        const int p = step & 1;
        // prefetch x@W+b contributions (DRAM/L2; consumed ~2000 cyc later)
        float z0 = g_Z[((size_t)(gb0 + bp * 2 + 0) * TT + step) * H4 + gcol];
        float z1 = g_Z[((size_t)(gb0 + bp * 2 + 1) * TT + step) * H4 + gcol];

        const float4* u4 = reinterpret_cast<const float4*>(Us + l * USTRIDE);
        const float4* hx = reinterpret_cast<const float4*>(hbuf + p * (GBAT * HH) + (bp * 2 + 0) * HH);
        const float4* hy = reinterpret_cast<const float4*>(hbuf + p * (GBAT * HH) + (bp * 2 + 1) * HH);

        float a0 = 0.0f, a1 = 0.0f;
        #pragma unroll 8
        for (int kk = 0; kk < 64; kk++) {
            float4 u = u4[kk];
            float4 x = hx[kk];
            float4 y = hy[kk];
            a0 = fmaf(u.x, x.x, a0); a0 = fmaf(u.y, x.y, a0);
            a0 = fmaf(u.z, x.z, a0); a0 = fmaf(u.w, x.w, a0);
            a1 = fmaf(u.x, y.x, a1); a1 = fmaf(u.y, y.y, a1);
            a1 = fmaf(u.z, y.z, a1); a1 = fmaf(u.w, y.w, a1);
        }
        zbuf[(gate * 32 + dl) * 4 + bp * 2 + 0] = z0 + a0;
        zbuf[(gate * 32 + dl) * 4 + bp * 2 + 1] = z1 + a1;
        __syncthreads();

        if (tid < 128) {
            float zi = zbuf[(0 * 32 + dc) * 4 + bc];
            float zf = zbuf[(1 * 32 + dc) * 4 + bc];
            float zg = zbuf[(2 * 32 + dc) * 4 + bc];
            float zo = zbuf[(3 * 32 + dc) * 4 + bc];
            float ig = sigmoidf_(zi);
            float fg = sigmoidf_(zf);
            creg = fg * creg + ig * fmaxf(zg, 0.0f);
            float hval = sigmoidf_(zo) * fmaxf(creg, 0.0f);

            g_seq[(size_t)(gb0 + bc) * KFLAT + step * HH + r * 32 + dc] = hval;

            uint32_t addr = hb_base +
                (uint32_t)(((p ^ 1) * (GBAT * HH) + bc * HH + r * 32 + dc) * 4);
            #pragma unroll
            for (int rk = 0; rk < CLSZ; rk++) {
                uint32_t ra;
                asm volatile("mapa.shared::cluster.u32 %0, %1, %2;"
                             : "=r"(ra) : "r"(addr), "r"(rk));
                asm volatile("st.shared::cluster.f32 [%0], %1;"
                             :: "r"(ra), "f"(hval) : "memory");
            }
            if (step == TT - 1) {
                outHT[(size_t)(gb0 + bc) * HH + r * 32 + dc] = hval;
                outCT[(size_t)(gb0 + bc) * HH + r * 32 + dc] = creg;
            }
        }
        asm volatile("barrier.cluster.arrive.aligned;\n" ::: "memory");
        asm volatile("barrier.cluster.wait.aligned;\n" ::: "memory");
    }
}

// =============================================================================
// Kernel C: dense split-K partials.
// part[kc][b][n] = sum_{k in chunk kc} seq[b][k] * Wd[k][n]
// M=64, N=256 (4 tiles of 64), K=118784 (116 chunks of 1024).
// BM=64, BN=64, BK=16, 256 threads, 4x4 per thread + register double-buffer.
// =============================================================================
__global__ __launch_bounds__(256) void gemm_dense_kernel(const float* __restrict__ Wd)
{
    __shared__ float As[16][64];
    __shared__ float Bs[16][64];

    const int tid = threadIdx.x;
    const int tx = tid & 15;
    const int ty = tid >> 4;
    const int nBase = blockIdx.x * 64;
    const int kc = blockIdx.y;
    const int kBase = kc * 1024;

    const int lmA = tid >> 2;          // 0..63
    const int lkA = (tid & 3) * 4;     // 0,4,8,12
    const int lkB = tid >> 4;          // 0..15
    const int lnB = (tid & 15) * 4;

    float acc[4][4];
    #pragma unroll
    for (int i = 0; i < 4; i++)
        #pragma unroll
        for (int j = 0; j < 4; j++) acc[i][j] = 0.0f;

    const float* aRow = &g_seq[(size_t)lmA * KFLAT + kBase + lkA];
    const float* wRow = &Wd[(size_t)(kBase + lkB) * HH + nBase + lnB];

    float4 pa = *reinterpret_cast<const float4*>(aRow);
    float4 pw = *reinterpret_cast<const float4*>(wRow);

    #pragma unroll 1
    for (int it = 0; it < 64; it++) {
        As[lkA + 0][lmA] = pa.x; As[lkA + 1][lmA] = pa.y;
        As[lkA + 2][lmA] = pa.z; As[lkA + 3][lmA] = pa.w;
        *reinterpret_cast<float4*>(&Bs[lkB][lnB]) = pw;
        __syncthreads();

        if (it < 63) {
            const int k0 = (it + 1) * 16;
            pa = *reinterpret_cast<const float4*>(aRow + k0);
            pw = *reinterpret_cast<const float4*>(wRow + (size_t)k0 * HH);
        }

        #pragma unroll
        for (int k = 0; k < 16; k++) {
            float4 a = *reinterpret_cast<const float4*>(&As[k][ty * 4]);
            float4 b = *reinterpret_cast<const float4*>(&Bs[k][tx * 4]);
            float ar[4] = {a.x, a.y, a.z, a.w};
            float br[4] = {b.x, b.y, b.z, b.w};
            #pragma unroll
            for (int i = 0; i < 4; i++)
                #pragma unroll
                for (int j = 0; j < 4; j++)
                    acc[i][j] = fmaf(ar[i], br[j], acc[i][j]);
        }
        __syncthreads();
    }

    #pragma unroll
    for (int i = 0; i < 4; i++) {
        float4 o;
        o.x = acc[i][0]; o.y = acc[i][1]; o.z = acc[i][2]; o.w = acc[i][3];
        *reinterpret_cast<float4*>(
            &g_part[((size_t)kc * 64 + ty * 4 + i) * HH + nBase + tx * 4]) = o;
    }
}

// Final reduce + bias + relu -> core_output.  256 CTAs x 128 thr, k-split 2.
__global__ __launch_bounds__(128) void reduce_dense_kernel(
    const float* __restrict__ bd, float* __restrict__ outCore)
{
    __shared__ float s2[128];
    const int b  = blockIdx.x >> 2;
    const int nq = blockIdx.x & 3;
    const int n  = nq * 64 + (threadIdx.x & 63);
    const int kh = threadIdx.x >> 6;
    float s = 0.0f;
    #pragma unroll 8
    for (int kc = kh; kc < NKC; kc += 2)
        s += g_part[((size_t)kc * 64 + b) * HH + n];
    s2[threadIdx.x] = s;
    __syncthreads();
    if (kh == 0)
        outCore[(size_t)b * HH + n] = fmaxf(s + s2[threadIdx.x + 64] + bd[n], 0.0f);
}

// =============================================================================
extern "C" void kernel_launch(void* const* d_in, const int* in_sizes, int n_in,
                              void* d_out, int out_size)
{
    const float* X  = (const float*)d_in[0];  // [64,464,256]
    const float* h0 = (const float*)d_in[1];  // [64,256]
    const float* c0 = (const float*)d_in[2];  // [64,256]
    const float* W  = (const float*)d_in[3];  // [256,1024]
    const float* U  = (const float*)d_in[4];  // [256,1024]
    const float* bb = (const float*)d_in[5];  // [1024]
    const float* Wd = (const float*)d_in[6];  // [118784,256]
    const float* bd = (const float*)d_in[7];  // [256]
    float* out = (float*)d_out;

    float* outCore = out;
    float* outHT;
    float* outCT;
    if (out_size >= 3 * BB * HH) {
        outHT = out + BB * HH;
        outCT = out + 2 * BB * HH;
    } else {
        float* dummy = nullptr;
        cudaGetSymbolAddress((void**)&dummy, g_dummy);
        outHT = dummy;
        outCT = dummy + BB * HH;
    }

    cudaFuncSetAttribute(lstm_kernel,
                         cudaFuncAttributeMaxDynamicSharedMemorySize,
                         LSTM_SMEM_BYTES);

    // 1) Z = X@W + b
    gemm_xw_kernel<<<dim3(H4 / 64, MROWS / 128), 256>>>(X, W, bb);

    // 2) recurrence (16 clusters x 8 CTAs)
    lstm_kernel<<<128, 256, LSTM_SMEM_BYTES>>>(U, h0, c0, outHT, outCT);

    // 3) dense split-K + reduce
    gemm_dense_kernel<<<dim3(HH / 64, NKC), 256>>>(Wd);
    reduce_dense_kernel<<<256, 128>>>(bd, outCore);
}